// round 6
// baseline (speedup 1.0000x reference)
#include <cuda_runtime.h>
#include <cuda_fp16.h>
#include <mma.h>
#include <cstdint>

#define NN 16384
#define EE 524288
#define EPAD (EE + 4 * NN)
#define BB 32
#define DD 64
#define MM 5

using namespace nvcuda;

// ---------------- device scratch (static, allocation-free) ----------------
// fp16 operand buffers, TRANSPOSED layout: buf[(n*32 + b)*64 + d]
__device__ __half g_Xh[(size_t)BB * NN * DD];
__device__ __half g_T1[(size_t)BB * NN * DD];
__device__ __half g_T2[(size_t)BB * NN * DD];
__device__ __half g_T3[(size_t)BB * NN * DD];
__device__ __half g_T4[(size_t)BB * NN * DD];

__device__ float g_degr[NN];
__device__ float g_degc[NN];
__device__ int   g_cnt1[NN], g_cnt2[NN];
__device__ int   g_ptr1[NN + 1], g_ptr2[NN + 1];
__device__ int   g_cur1[NN], g_cur2[NN];
__device__ int   g_src1[EPAD], g_src2[EPAD];
__device__ float g_val1[EPAD], g_val2[EPAD];

// ---------------- init (split per-CSR so the two chains can overlap) ----------------
__global__ void k_zero1() {
    int i = blockIdx.x * blockDim.x + threadIdx.x;
    if (i < NN) { g_degr[i] = 0.f; g_cnt1[i] = 0; }
}
__global__ void k_zero2() {
    int i = blockIdx.x * blockDim.x + threadIdx.x;
    if (i < NN) { g_degc[i] = 0.f; g_cnt2[i] = 0; }
}

__global__ void k_degree1(const int* __restrict__ rows, const int* __restrict__ cols,
                          const float* __restrict__ adj) {
    int e = blockIdx.x * blockDim.x + threadIdx.x;
    if (e >= EE) return;
    atomicAdd(&g_degr[rows[e]], adj[e]);
    atomicAdd(&g_cnt1[cols[e]], 1);     // S1 scatters to cols
}
__global__ void k_degree2(const int* __restrict__ rows, const int* __restrict__ cols,
                          const float* __restrict__ adj) {
    int e = blockIdx.x * blockDim.x + threadIdx.x;
    if (e >= EE) return;
    atomicAdd(&g_degc[cols[e]], adj[e]);
    atomicAdd(&g_cnt2[rows[e]], 1);     // S2 scatters to rows
}

// single-block exclusive scan; segments rounded up to multiple of 4, pads zeroed
__device__ void scan16k(const int* __restrict__ cnt, int* __restrict__ ptr,
                        int* __restrict__ cur, int* __restrict__ src,
                        float* __restrict__ val, int* sh) {
    int t = threadIdx.x;
    int base = t * 16;
    int loc[16], cr[16], cn[16];
    int s = 0;
#pragma unroll
    for (int j = 0; j < 16; ++j) {
        cn[j] = cnt[base + j];
        cr[j] = (cn[j] + 3) & ~3;       // padded segment length
        loc[j] = s; s += cr[j];
    }
    sh[t] = s;
    __syncthreads();
    for (int off = 1; off < 1024; off <<= 1) {
        int v = (t >= off) ? sh[t - off] : 0;
        __syncthreads();
        sh[t] += v;
        __syncthreads();
    }
    int pre = (t == 0) ? 0 : sh[t - 1];
#pragma unroll
    for (int j = 0; j < 16; ++j) {
        int p = pre + loc[j];
        ptr[base + j] = p;
        cur[base + j] = p;
        for (int q = p + cn[j]; q < p + cr[j]; ++q) { src[q] = 0; val[q] = 0.f; }
    }
    if (t == 1023) ptr[NN] = sh[1023];
    __syncthreads();
}

__global__ void k_scan1() {
    __shared__ int sh[1024];
    scan16k(g_cnt1, g_ptr1, g_cur1, g_src1, g_val1, sh);
    int t = threadIdx.x;
    for (int i = t; i < NN; i += 1024) {
        float d = g_degr[i]; g_degr[i] = (d > 0.f) ? 1.f / d : 0.f;
    }
}
__global__ void k_scan2() {
    __shared__ int sh[1024];
    scan16k(g_cnt2, g_ptr2, g_cur2, g_src2, g_val2, sh);
    int t = threadIdx.x;
    for (int i = t; i < NN; i += 1024) {
        float d = g_degc[i]; g_degc[i] = (d > 0.f) ? 1.f / d : 0.f;
    }
}

__global__ void k_fill1(const int* __restrict__ rows, const int* __restrict__ cols,
                        const float* __restrict__ adj) {
    int e = blockIdx.x * blockDim.x + threadIdx.x;
    if (e >= EE) return;
    int r = rows[e], c = cols[e];
    int p = atomicAdd(&g_cur1[c], 1);
    g_src1[p] = r;
    g_val1[p] = adj[e] * g_degr[r];
}
__global__ void k_fill2(const int* __restrict__ rows, const int* __restrict__ cols,
                        const float* __restrict__ adj) {
    int e = blockIdx.x * blockDim.x + threadIdx.x;
    if (e >= EE) return;
    int r = rows[e], c = cols[e];
    int q = atomicAdd(&g_cur2[r], 1);
    g_src2[q] = c;
    g_val2[q] = adj[e] * g_degc[c];
}

// ---------------- convert ----------------
// inputs [b][n][d] fp32 -> g_Xh [(n*32+b)*64+d] fp16 (transpose b<->n)
__global__ void k_cvt_x(const float* __restrict__ X) {
    int i = blockIdx.x * blockDim.x + threadIdx.x;     // half2 index in TARGET
    if (i >= BB * NN * (DD / 2)) return;
    int dh = i & 31;
    int b  = (i >> 5) & 31;
    int n  = i >> 10;
    float2 v = ((const float2*)X)[((size_t)b * NN + n) * 32 + dh];
    ((__half2*)g_Xh)[i] = __floats2half2_rn(v.x, v.y);
}

// ---------------- SpMM (R3/R5-proven): warp = (dst node, 4 batches), LDG.128, MLP=4 ----------------
__device__ __forceinline__ void acc8(float2* acc, uint4 g, float v) {
    __half2* h = (__half2*)&g;
#pragma unroll
    for (int k = 0; k < 4; ++k) {
        float2 f = __half22float2(h[k]);
        acc[k].x = fmaf(v, f.x, acc[k].x);
        acc[k].y = fmaf(v, f.y, acc[k].y);
    }
}

template <bool CHEB>
__global__ void __launch_bounds__(256) k_spmm(
    const int* __restrict__ ptr, const int* __restrict__ srcs,
    const float* __restrict__ vals, const __half* __restrict__ X,
    const __half* __restrict__ XM, __half* __restrict__ T)
{
    int lane = threadIdx.x & 31;
    int n = blockIdx.x * 8 + (threadIdx.x >> 5);
    int quad = blockIdx.y;                               // batches [quad*4, quad*4+4)
    int sub = (quad * 4 + (lane >> 3)) * 8 + (lane & 7); // uint4 index within 4KB node block
    const uint4* __restrict__ Xb = (const uint4*)X;

    int p0 = ptr[n], p1 = ptr[n + 1];                    // segment length multiple of 4
    float2 acc[4] = {{0.f,0.f},{0.f,0.f},{0.f,0.f},{0.f,0.f}};

    for (int base = p0; base < p1; base += 32) {
        int idx = base + lane;
        int s = 0; float v = 0.f;
        if (idx < p1) { s = srcs[idx]; v = vals[idx]; }
        int cnt = min(32, p1 - base);                    // multiple of 4
        for (int j = 0; j < cnt; j += 4) {
            int s0 = __shfl_sync(0xffffffffu, s, j);
            int s1 = __shfl_sync(0xffffffffu, s, j + 1);
            int s2 = __shfl_sync(0xffffffffu, s, j + 2);
            int s3 = __shfl_sync(0xffffffffu, s, j + 3);
            float v0 = __shfl_sync(0xffffffffu, v, j);
            float v1 = __shfl_sync(0xffffffffu, v, j + 1);
            float v2 = __shfl_sync(0xffffffffu, v, j + 2);
            float v3 = __shfl_sync(0xffffffffu, v, j + 3);
            uint4 g0 = Xb[s0 * 256 + sub];
            uint4 g1 = Xb[s1 * 256 + sub];
            uint4 g2 = Xb[s2 * 256 + sub];
            uint4 g3 = Xb[s3 * 256 + sub];
            acc8(acc, g0, v0);
            acc8(acc, g1, v1);
            acc8(acc, g2, v2);
            acc8(acc, g3, v3);
        }
    }

    size_t o = (size_t)n * 256 + sub;                    // uint4 units
    if (CHEB) {
        uint4 mg = ((const uint4*)XM)[o];
        __half2* mh = (__half2*)&mg;
#pragma unroll
        for (int k = 0; k < 4; ++k) {
            float2 f = __half22float2(mh[k]);
            acc[k].x = 2.f * acc[k].x - f.x;
            acc[k].y = 2.f * acc[k].y - f.y;
        }
    }
    uint4 r;
    __half2* rh = (__half2*)&r;
#pragma unroll
    for (int k = 0; k < 4; ++k) rh[k] = __floats2half2_rn(acc[k].x, acc[k].y);
    ((uint4*)T)[o] = r;
}

// ---------------- tensor-core projection (W convert fused into smem fill) ----------------
// 1024 blocks x 8 warps; each warp sweeps 4 consecutive 16-row tiles.
__global__ void __launch_bounds__(256) k_gemm_tc(
    const __half* __restrict__ Xh, const __half* __restrict__ T1,
    const __half* __restrict__ T2, const __half* __restrict__ T3,
    const __half* __restrict__ T4, const float* __restrict__ W,
    const float* __restrict__ bias, float* __restrict__ out)
{
    __shared__ __half Wsh[MM * DD * DD];        // 40 KB, loaded + converted ONCE per block
    __shared__ float  Bsh[16 * 64];
    int tid = threadIdx.x;
    int warp = tid >> 5;

    // Wsh[(m*64+k)*64+o] = half(W[(k*5+m)*64+o]) — float4-vectorized permute+convert
#pragma unroll
    for (int i = tid; i < MM * DD * DD / 4; i += 256) {
        int m  = i >> 10;           // i / 1024
        int k  = (i >> 4) & 63;
        int o4 = i & 15;
        float4 v = *(const float4*)(W + (size_t)(k * MM + m) * DD + o4 * 4);
        ((__half2*)Wsh)[(m * 64 + k) * 32 + o4 * 2]     = __floats2half2_rn(v.x, v.y);
        ((__half2*)Wsh)[(m * 64 + k) * 32 + o4 * 2 + 1] = __floats2half2_rn(v.z, v.w);
    }
#pragma unroll
    for (int i = tid; i < 16 * 64; i += 256) Bsh[i] = bias[i & 63];
    __syncthreads();

    const __half* bufs[5] = {Xh, T1, T2, T3, T4};

#pragma unroll
    for (int t = 0; t < 4; ++t) {
        int tile = (blockIdx.x * 8 + warp) * 4 + t;
        int r0 = tile * 16;                 // global A row
        int n  = r0 >> 5;
        int b0 = r0 & 31;                   // 0 or 16

        wmma::fragment<wmma::accumulator, 16, 16, 16, float> c[4];
#pragma unroll
        for (int j = 0; j < 4; ++j)
            wmma::load_matrix_sync(c[j], &Bsh[j * 16], 64, wmma::mem_row_major);

#pragma unroll
        for (int m = 0; m < 5; ++m) {
            const __half* A = bufs[m] + (size_t)r0 * DD;
#pragma unroll
            for (int kt = 0; kt < 4; ++kt) {
                wmma::fragment<wmma::matrix_a, 16, 16, 16, __half, wmma::row_major> a;
                wmma::load_matrix_sync(a, A + kt * 16, 64);
#pragma unroll
                for (int j = 0; j < 4; ++j) {
                    wmma::fragment<wmma::matrix_b, 16, 16, 16, __half, wmma::row_major> b;
                    wmma::load_matrix_sync(b, &Wsh[(m * 64 + kt * 16) * 64 + j * 16], 64);
                    wmma::mma_sync(c[j], a, b, c[j]);
                }
            }
        }
        float* ob = out + ((size_t)b0 * NN + n) * DD;
#pragma unroll
        for (int j = 0; j < 4; ++j)
            wmma::store_matrix_sync(ob + j * 16, c[j], NN * DD, wmma::mem_row_major);
    }
}

// ---------------- launch: two-branch capture topology ----------------
extern "C" void kernel_launch(void* const* d_in, const int* in_sizes, int n_in,
                              void* d_out, int out_size)
{
    const float* inputs  = (const float*)d_in[0];   // [B, N, D]
    const float* adj     = (const float*)d_in[1];   // [E]
    const int*   rows    = (const int*)d_in[2];     // [E]
    const int*   cols    = (const int*)d_in[3];     // [E]
    const float* weights = (const float*)d_in[4];   // [D*M, OUT]
    const float* biases  = (const float*)d_in[5];   // [1, OUT]
    float* out = (float*)d_out;                     // [B, N, OUT]
    (void)in_sizes; (void)n_in; (void)out_size;

    // one-time lightweight event handles (no device memory; work is identical every call)
    static cudaEvent_t ev0 = nullptr, evX = nullptr, evP1 = nullptr, evP3 = nullptr;
    if (ev0 == nullptr) {
        cudaEventCreateWithFlags(&ev0,  cudaEventDisableTiming);
        cudaEventCreateWithFlags(&evX,  cudaEventDisableTiming);
        cudaEventCreateWithFlags(&evP1, cudaEventDisableTiming);
        cudaEventCreateWithFlags(&evP3, cudaEventDisableTiming);
    }
    cudaStream_t spt = cudaStreamPerThread;   // built-in non-blocking stream, no creation

    void *pP1, *pP2, *pS1, *pS2, *pV1, *pV2, *pX, *pT1, *pT2, *pT3, *pT4;
    cudaGetSymbolAddress(&pP1, g_ptr1);
    cudaGetSymbolAddress(&pP2, g_ptr2);
    cudaGetSymbolAddress(&pS1, g_src1);
    cudaGetSymbolAddress(&pS2, g_src2);
    cudaGetSymbolAddress(&pV1, g_val1);
    cudaGetSymbolAddress(&pV2, g_val2);
    cudaGetSymbolAddress(&pX,  g_Xh);
    cudaGetSymbolAddress(&pT1, g_T1);
    cudaGetSymbolAddress(&pT2, g_T2);
    cudaGetSymbolAddress(&pT3, g_T3);
    cudaGetSymbolAddress(&pT4, g_T4);

    dim3 sg(NN / 8, 8);

    // fork: bring the side stream into the capture
    cudaEventRecord(ev0, 0);
    cudaStreamWaitEvent(spt, ev0, 0);

    // ---- side branch: X convert, then CSR2 build (needed first by pass3) ----
    k_cvt_x<<<(BB * NN * (DD / 2) + 255) / 256, 256, 0, spt>>>(inputs);
    cudaEventRecord(evX, spt);
    k_zero2<<<(NN + 255) / 256, 256, 0, spt>>>();
    k_degree2<<<(EE + 255) / 256, 256, 0, spt>>>(rows, cols, adj);
    k_scan2<<<1, 1024, 0, spt>>>();
    k_fill2<<<(EE + 255) / 256, 256, 0, spt>>>(rows, cols, adj);

    // ---- main branch: CSR1 build ----
    k_zero1<<<(NN + 255) / 256, 256>>>();
    k_degree1<<<(EE + 255) / 256, 256>>>(rows, cols, adj);
    k_scan1<<<1, 1024>>>();
    k_fill1<<<(EE + 255) / 256, 256>>>(rows, cols, adj);

    // pass1 = S1 @ X0 (needs CSR1 + Xh)
    cudaStreamWaitEvent(0, evX, 0);
    k_spmm<false><<<sg, 256>>>((const int*)pP1, (const int*)pS1, (const float*)pV1,
                               (const __half*)pX, nullptr, (__half*)pT1);
    cudaEventRecord(evP1, 0);

    // side: pass3 = S2 @ T1 (needs CSR2 [in-order on spt] + T1)
    cudaStreamWaitEvent(spt, evP1, 0);
    k_spmm<false><<<sg, 256, 0, spt>>>((const int*)pP2, (const int*)pS2, (const float*)pV2,
                                       (const __half*)pT1, nullptr, (__half*)pT3);
    cudaEventRecord(evP3, spt);

    // main: pass2 = 2*S1 @ T1 - X0 (concurrent with pass3)
    k_spmm<true><<<sg, 256>>>((const int*)pP1, (const int*)pS1, (const float*)pV1,
                              (const __half*)pT1, (const __half*)pX, (__half*)pT2);

    // pass4 = 2*S2 @ T3 - T1 (needs pass3; pass2 ordered on this stream)
    cudaStreamWaitEvent(0, evP3, 0);
    k_spmm<true><<<sg, 256>>>((const int*)pP2, (const int*)pS2, (const float*)pV2,
                              (const __half*)pT3, (const __half*)pT1, (__half*)pT4);

    // projection
    k_gemm_tc<<<(BB * NN) / (4 * 8 * 16), 256>>>((const __half*)pX, (const __half*)pT1,
                                                 (const __half*)pT2, (const __half*)pT3,
                                                 (const __half*)pT4, weights, biases, out);
}

// round 7
// speedup vs baseline: 1.1066x; 1.1066x over previous
#include <cuda_runtime.h>
#include <cuda_fp16.h>
#include <mma.h>
#include <cstdint>

#define NN 16384
#define EE 524288
#define EPAD (EE + 4 * NN)
#define BB 32
#define DD 64
#define MM 5

using namespace nvcuda;

// ---------------- device scratch (static, allocation-free) ----------------
// fp16 operand buffers, TRANSPOSED layout: buf[(n*32 + b)*64 + d]
__device__ __half g_Xh[(size_t)BB * NN * DD];
__device__ __half g_T1[(size_t)BB * NN * DD];
__device__ __half g_T2[(size_t)BB * NN * DD];
__device__ __half g_T3[(size_t)BB * NN * DD];
__device__ __half g_T4[(size_t)BB * NN * DD];

__device__ float g_degr[NN];
__device__ float g_degc[NN];
__device__ int   g_cnt1[NN], g_cnt2[NN];
__device__ int   g_ptr1[NN + 1], g_ptr2[NN + 1];
__device__ int   g_cur1[NN], g_cur2[NN];
__device__ int   g_src1[EPAD], g_src2[EPAD];
__device__ float g_val1[EPAD], g_val2[EPAD];

// scan intermediates
__device__ int g_locpre[2][NN];
__device__ int g_bsum[2][16];
__device__ int g_boff[2][16];

// ---------------- init ----------------
__global__ void k_zero() {
    int i = blockIdx.x * blockDim.x + threadIdx.x;
    if (i < NN) {
        g_degr[i] = 0.f; g_degc[i] = 0.f;
        g_cnt1[i] = 0;   g_cnt2[i] = 0;
    }
}

// fused: one edge-list read feeds both CSR histograms + both degree sums
__global__ void k_degree(const int* __restrict__ rows, const int* __restrict__ cols,
                         const float* __restrict__ adj) {
    int e = blockIdx.x * blockDim.x + threadIdx.x;
    if (e >= EE) return;
    int r = rows[e], c = cols[e];
    float a = adj[e];
    atomicAdd(&g_degr[r], a);
    atomicAdd(&g_degc[c], a);
    atomicAdd(&g_cnt1[c], 1);   // S1 scatters to cols
    atomicAdd(&g_cnt2[r], 1);   // S2 scatters to rows
}

// ---------------- parallel 3-phase scan (both CSRs via blockIdx.y) ----------------
// Phase A: per-block (1024 counts) exclusive scan of padded counts
__global__ void __launch_bounds__(1024) k_scanA() {
    int y = blockIdx.y;
    const int* cnt = y ? g_cnt2 : g_cnt1;
    int i = blockIdx.x * 1024 + threadIdx.x;
    int c = (cnt[i] + 3) & ~3;
    int lane = threadIdx.x & 31, w = threadIdx.x >> 5;
    int x = c;
#pragma unroll
    for (int o = 1; o < 32; o <<= 1) {
        int t = __shfl_up_sync(0xffffffffu, x, o);
        if (lane >= o) x += t;
    }
    __shared__ int wsum[32];
    if (lane == 31) wsum[w] = x;
    __syncthreads();
    if (w == 0) {
        int t = wsum[lane];
#pragma unroll
        for (int o = 1; o < 32; o <<= 1) {
            int u = __shfl_up_sync(0xffffffffu, t, o);
            if (lane >= o) t += u;
        }
        wsum[lane] = t;
    }
    __syncthreads();
    int pre = x - c + (w ? wsum[w - 1] : 0);
    g_locpre[y][i] = pre;
    if (threadIdx.x == 1023) g_bsum[y][blockIdx.x] = pre + c;
}

// Phase B: scan the 16 block partials (both CSRs), write ptr[NN]
__global__ void k_scanB() {
    int lane = threadIdx.x;
#pragma unroll
    for (int y = 0; y < 2; ++y) {
        int v = (lane < 16) ? g_bsum[y][lane] : 0;
        int x = v;
#pragma unroll
        for (int o = 1; o < 32; o <<= 1) {
            int t = __shfl_up_sync(0xffffffffu, x, o);
            if (lane >= o) x += t;
        }
        if (lane < 16) g_boff[y][lane] = x - v;
        if (lane == 15) (y ? g_ptr2 : g_ptr1)[NN] = x;
    }
}

// Phase C: finalize ptr/cur, zero pad slots, invert degrees — fully parallel
__global__ void __launch_bounds__(1024) k_scanC() {
    int y = blockIdx.y;
    int i = blockIdx.x * 1024 + threadIdx.x;
    const int* cnt = y ? g_cnt2 : g_cnt1;
    int* ptr = y ? g_ptr2 : g_ptr1;
    int* cur = y ? g_cur2 : g_cur1;
    int* src = y ? g_src2 : g_src1;
    float* val = y ? g_val2 : g_val1;
    int p = g_boff[y][blockIdx.x] + g_locpre[y][i];
    ptr[i] = p; cur[i] = p;
    int cn = cnt[i], cr = (cn + 3) & ~3;
    for (int q = p + cn; q < p + cr; ++q) { src[q] = 0; val[q] = 0.f; }
    float* dg = y ? g_degc : g_degr;
    float d = dg[i];
    dg[i] = (d > 0.f) ? 1.f / d : 0.f;
}

// fused: one edge-list read fills both CSRs
__global__ void k_fill(const int* __restrict__ rows, const int* __restrict__ cols,
                       const float* __restrict__ adj) {
    int e = blockIdx.x * blockDim.x + threadIdx.x;
    if (e >= EE) return;
    int r = rows[e], c = cols[e];
    float a = adj[e];
    int p = atomicAdd(&g_cur1[c], 1);
    g_src1[p] = r;
    g_val1[p] = a * g_degr[r];
    int q = atomicAdd(&g_cur2[r], 1);
    g_src2[q] = c;
    g_val2[q] = a * g_degc[c];
}

// ---------------- convert ----------------
// inputs [b][n][d] fp32 -> g_Xh [(n*32+b)*64+d] fp16 (transpose b<->n)
__global__ void k_cvt_x(const float* __restrict__ X) {
    int i = blockIdx.x * blockDim.x + threadIdx.x;     // half2 index in TARGET
    if (i >= BB * NN * (DD / 2)) return;
    int dh = i & 31;
    int b  = (i >> 5) & 31;
    int n  = i >> 10;
    float2 v = ((const float2*)X)[((size_t)b * NN + n) * 32 + dh];
    ((__half2*)g_Xh)[i] = __floats2half2_rn(v.x, v.y);
}

// ---------------- SpMM (R3/R5-proven): warp = (dst node, 4 batches), LDG.128, MLP=4 ----------------
__device__ __forceinline__ void acc8(float2* acc, uint4 g, float v) {
    __half2* h = (__half2*)&g;
#pragma unroll
    for (int k = 0; k < 4; ++k) {
        float2 f = __half22float2(h[k]);
        acc[k].x = fmaf(v, f.x, acc[k].x);
        acc[k].y = fmaf(v, f.y, acc[k].y);
    }
}

template <bool CHEB>
__global__ void __launch_bounds__(256) k_spmm(
    const int* __restrict__ ptr, const int* __restrict__ srcs,
    const float* __restrict__ vals, const __half* __restrict__ X,
    const __half* __restrict__ XM, __half* __restrict__ T)
{
    int lane = threadIdx.x & 31;
    int n = blockIdx.x * 8 + (threadIdx.x >> 5);
    int quad = blockIdx.y;                               // batches [quad*4, quad*4+4)
    int sub = (quad * 4 + (lane >> 3)) * 8 + (lane & 7); // uint4 index within 4KB node block
    const uint4* __restrict__ Xb = (const uint4*)X;

    int p0 = ptr[n], p1 = ptr[n + 1];                    // segment length multiple of 4
    float2 acc[4] = {{0.f,0.f},{0.f,0.f},{0.f,0.f},{0.f,0.f}};

    for (int base = p0; base < p1; base += 32) {
        int idx = base + lane;
        int s = 0; float v = 0.f;
        if (idx < p1) { s = srcs[idx]; v = vals[idx]; }
        int cnt = min(32, p1 - base);                    // multiple of 4
        for (int j = 0; j < cnt; j += 4) {
            int s0 = __shfl_sync(0xffffffffu, s, j);
            int s1 = __shfl_sync(0xffffffffu, s, j + 1);
            int s2 = __shfl_sync(0xffffffffu, s, j + 2);
            int s3 = __shfl_sync(0xffffffffu, s, j + 3);
            float v0 = __shfl_sync(0xffffffffu, v, j);
            float v1 = __shfl_sync(0xffffffffu, v, j + 1);
            float v2 = __shfl_sync(0xffffffffu, v, j + 2);
            float v3 = __shfl_sync(0xffffffffu, v, j + 3);
            uint4 g0 = Xb[s0 * 256 + sub];
            uint4 g1 = Xb[s1 * 256 + sub];
            uint4 g2 = Xb[s2 * 256 + sub];
            uint4 g3 = Xb[s3 * 256 + sub];
            acc8(acc, g0, v0);
            acc8(acc, g1, v1);
            acc8(acc, g2, v2);
            acc8(acc, g3, v3);
        }
    }

    size_t o = (size_t)n * 256 + sub;                    // uint4 units
    if (CHEB) {
        uint4 mg = ((const uint4*)XM)[o];
        __half2* mh = (__half2*)&mg;
#pragma unroll
        for (int k = 0; k < 4; ++k) {
            float2 f = __half22float2(mh[k]);
            acc[k].x = 2.f * acc[k].x - f.x;
            acc[k].y = 2.f * acc[k].y - f.y;
        }
    }
    uint4 r;
    __half2* rh = (__half2*)&r;
#pragma unroll
    for (int k = 0; k < 4; ++k) rh[k] = __floats2half2_rn(acc[k].x, acc[k].y);
    ((uint4*)T)[o] = r;
}

// ---------------- tensor-core projection (W convert fused into smem fill) ----------------
// 1024 blocks x 8 warps; each warp sweeps 4 consecutive 16-row tiles.
__global__ void __launch_bounds__(256) k_gemm_tc(
    const __half* __restrict__ Xh, const __half* __restrict__ T1,
    const __half* __restrict__ T2, const __half* __restrict__ T3,
    const __half* __restrict__ T4, const float* __restrict__ W,
    const float* __restrict__ bias, float* __restrict__ out)
{
    __shared__ __half Wsh[MM * DD * DD];        // 40 KB, loaded + converted ONCE per block
    __shared__ float  Bsh[16 * 64];
    int tid = threadIdx.x;
    int warp = tid >> 5;

    // Wsh[(m*64+k)*64+o] = half(W[(k*5+m)*64+o]) — float4-vectorized permute+convert
#pragma unroll
    for (int i = tid; i < MM * DD * DD / 4; i += 256) {
        int m  = i >> 10;           // i / 1024
        int k  = (i >> 4) & 63;
        int o4 = i & 15;
        float4 v = *(const float4*)(W + (size_t)(k * MM + m) * DD + o4 * 4);
        ((__half2*)Wsh)[(m * 64 + k) * 32 + o4 * 2]     = __floats2half2_rn(v.x, v.y);
        ((__half2*)Wsh)[(m * 64 + k) * 32 + o4 * 2 + 1] = __floats2half2_rn(v.z, v.w);
    }
#pragma unroll
    for (int i = tid; i < 16 * 64; i += 256) Bsh[i] = bias[i & 63];
    __syncthreads();

    const __half* bufs[5] = {Xh, T1, T2, T3, T4};

#pragma unroll
    for (int t = 0; t < 4; ++t) {
        int tile = (blockIdx.x * 8 + warp) * 4 + t;
        int r0 = tile * 16;                 // global A row
        int n  = r0 >> 5;
        int b0 = r0 & 31;                   // 0 or 16

        wmma::fragment<wmma::accumulator, 16, 16, 16, float> c[4];
#pragma unroll
        for (int j = 0; j < 4; ++j)
            wmma::load_matrix_sync(c[j], &Bsh[j * 16], 64, wmma::mem_row_major);

#pragma unroll
        for (int m = 0; m < 5; ++m) {
            const __half* A = bufs[m] + (size_t)r0 * DD;
#pragma unroll
            for (int kt = 0; kt < 4; ++kt) {
                wmma::fragment<wmma::matrix_a, 16, 16, 16, __half, wmma::row_major> a;
                wmma::load_matrix_sync(a, A + kt * 16, 64);
#pragma unroll
                for (int j = 0; j < 4; ++j) {
                    wmma::fragment<wmma::matrix_b, 16, 16, 16, __half, wmma::row_major> b;
                    wmma::load_matrix_sync(b, &Wsh[(m * 64 + kt * 16) * 64 + j * 16], 64);
                    wmma::mma_sync(c[j], a, b, c[j]);
                }
            }
        }
        float* ob = out + ((size_t)b0 * NN + n) * DD;
#pragma unroll
        for (int j = 0; j < 4; ++j)
            wmma::store_matrix_sync(ob + j * 16, c[j], NN * DD, wmma::mem_row_major);
    }
}

// ---------------- launch (single stream, R5 topology + fast scan) ----------------
extern "C" void kernel_launch(void* const* d_in, const int* in_sizes, int n_in,
                              void* d_out, int out_size)
{
    const float* inputs  = (const float*)d_in[0];   // [B, N, D]
    const float* adj     = (const float*)d_in[1];   // [E]
    const int*   rows    = (const int*)d_in[2];     // [E]
    const int*   cols    = (const int*)d_in[3];     // [E]
    const float* weights = (const float*)d_in[4];   // [D*M, OUT]
    const float* biases  = (const float*)d_in[5];   // [1, OUT]
    float* out = (float*)d_out;                     // [B, N, OUT]
    (void)in_sizes; (void)n_in; (void)out_size;

    void *pP1, *pP2, *pS1, *pS2, *pV1, *pV2, *pX, *pT1, *pT2, *pT3, *pT4;
    cudaGetSymbolAddress(&pP1, g_ptr1);
    cudaGetSymbolAddress(&pP2, g_ptr2);
    cudaGetSymbolAddress(&pS1, g_src1);
    cudaGetSymbolAddress(&pS2, g_src2);
    cudaGetSymbolAddress(&pV1, g_val1);
    cudaGetSymbolAddress(&pV2, g_val2);
    cudaGetSymbolAddress(&pX,  g_Xh);
    cudaGetSymbolAddress(&pT1, g_T1);
    cudaGetSymbolAddress(&pT2, g_T2);
    cudaGetSymbolAddress(&pT3, g_T3);
    cudaGetSymbolAddress(&pT4, g_T4);

    k_zero<<<(NN + 255) / 256, 256>>>();
    k_degree<<<(EE + 255) / 256, 256>>>(rows, cols, adj);
    k_scanA<<<dim3(16, 2), 1024>>>();
    k_scanB<<<1, 32>>>();
    k_scanC<<<dim3(16, 2), 1024>>>();
    k_fill<<<(EE + 255) / 256, 256>>>(rows, cols, adj);
    k_cvt_x<<<(BB * NN * (DD / 2) + 255) / 256, 256>>>(inputs);

    dim3 sg(NN / 8, 8);
    // T1 = S1 @ X0
    k_spmm<false><<<sg, 256>>>((const int*)pP1, (const int*)pS1, (const float*)pV1,
                               (const __half*)pX, nullptr, (__half*)pT1);
    // T2 = 2*S1 @ T1 - X0
    k_spmm<true><<<sg, 256>>>((const int*)pP1, (const int*)pS1, (const float*)pV1,
                              (const __half*)pT1, (const __half*)pX, (__half*)pT2);
    // T3 = S2 @ T1
    k_spmm<false><<<sg, 256>>>((const int*)pP2, (const int*)pS2, (const float*)pV2,
                               (const __half*)pT1, nullptr, (__half*)pT3);
    // T4 = 2*S2 @ T3 - T1
    k_spmm<true><<<sg, 256>>>((const int*)pP2, (const int*)pS2, (const float*)pV2,
                              (const __half*)pT3, (const __half*)pT1, (__half*)pT4);

    k_gemm_tc<<<(BB * NN) / (4 * 8 * 16), 256>>>((const __half*)pX, (const __half*)pT1,
                                                 (const __half*)pT2, (const __half*)pT3,
                                                 (const __half*)pT4, weights, biases, out);
}

// round 9
// speedup vs baseline: 1.1109x; 1.0039x over previous
#include <cuda_runtime.h>
#include <cuda_fp16.h>
#include <mma.h>
#include <cstdint>

#define NN 16384
#define EE 524288
#define EPAD (EE + 4 * NN)
#define BB 32
#define DD 64
#define MM 5

using namespace nvcuda;

// ---------------- device scratch (static, allocation-free) ----------------
// fp16 operand buffers, TRANSPOSED layout: buf[(n*32 + b)*64 + d]
__device__ __half g_Xh[(size_t)BB * NN * DD];
__device__ __half g_T1[(size_t)BB * NN * DD];
__device__ __half g_T2[(size_t)BB * NN * DD];
__device__ __half g_T3[(size_t)BB * NN * DD];
__device__ __half g_T4[(size_t)BB * NN * DD];

__device__ float g_degr[NN];
__device__ float g_degc[NN];
__device__ int   g_cnt1[NN], g_cnt2[NN];
__device__ int   g_ptr1[NN + 1], g_ptr2[NN + 1];
__device__ int   g_cur1[NN], g_cur2[NN];
__device__ int   g_src1[EPAD], g_src2[EPAD];
__device__ float g_val1[EPAD], g_val2[EPAD];

// scan intermediates
__device__ int g_locpre[2][NN];
__device__ int g_bsum[2][16];

#define CVT_BLOCKS 65536   // BB*NN*DD/2 half2 elems / 256 threads
#define EDGE_BLOCKS 2048   // EE / 256

// ---------------- init ----------------
__global__ void k_zero() {
    int i = blockIdx.x * blockDim.x + threadIdx.x;
    if (i < NN) {
        g_degr[i] = 0.f; g_degc[i] = 0.f;
        g_cnt1[i] = 0;   g_cnt2[i] = 0;
    }
}

// fused: blocks [0,EDGE_BLOCKS) = degree/histogram atomics;
//        blocks [EDGE_BLOCKS, EDGE_BLOCKS+CVT_BLOCKS) = X transpose-convert.
// inputs [b][n][d] fp32 -> g_Xh [(n*32+b)*64+d] fp16 (transpose b<->n)
__global__ void k_pre(const int* __restrict__ rows, const int* __restrict__ cols,
                      const float* __restrict__ adj, const float* __restrict__ X) {
    int bx = blockIdx.x;
    if (bx < EDGE_BLOCKS) {
        int e = bx * 256 + threadIdx.x;
        if (e >= EE) return;
        int r = rows[e], c = cols[e];
        float a = adj[e];
        atomicAdd(&g_degr[r], a);
        atomicAdd(&g_degc[c], a);
        atomicAdd(&g_cnt1[c], 1);   // S1 scatters to cols
        atomicAdd(&g_cnt2[r], 1);   // S2 scatters to rows
    } else {
        int i = (bx - EDGE_BLOCKS) * 256 + threadIdx.x;   // half2 index in TARGET
        if (i >= BB * NN * (DD / 2)) return;
        int dh = i & 31;
        int b  = (i >> 5) & 31;
        int n  = i >> 10;
        float2 v = ((const float2*)X)[((size_t)b * NN + n) * 32 + dh];
        ((__half2*)g_Xh)[i] = __floats2half2_rn(v.x, v.y);
    }
}

// ---------------- parallel scan (both CSRs via blockIdx.y) ----------------
// Phase A: per-block (1024 counts) exclusive scan of padded counts
__global__ void __launch_bounds__(1024) k_scanA() {
    int y = blockIdx.y;
    const int* cnt = y ? g_cnt2 : g_cnt1;
    int i = blockIdx.x * 1024 + threadIdx.x;
    int c = (cnt[i] + 3) & ~3;
    int lane = threadIdx.x & 31, w = threadIdx.x >> 5;
    int x = c;
#pragma unroll
    for (int o = 1; o < 32; o <<= 1) {
        int t = __shfl_up_sync(0xffffffffu, x, o);
        if (lane >= o) x += t;
    }
    __shared__ int wsum[32];
    if (lane == 31) wsum[w] = x;
    __syncthreads();
    if (w == 0) {
        int t = wsum[lane];
#pragma unroll
        for (int o = 1; o < 32; o <<= 1) {
            int u = __shfl_up_sync(0xffffffffu, t, o);
            if (lane >= o) t += u;
        }
        wsum[lane] = t;
    }
    __syncthreads();
    int pre = x - c + (w ? wsum[w - 1] : 0);
    g_locpre[y][i] = pre;
    if (threadIdx.x == 1023) g_bsum[y][blockIdx.x] = pre + c;
}

// Phase C (with inlined 16-partial scan): finalize ptr/cur, zero pads, invert degrees
__global__ void __launch_bounds__(1024) k_scanC() {
    int y = blockIdx.y;
    int bx = blockIdx.x;
    int boff = 0, tot = 0;
#pragma unroll
    for (int j = 0; j < 16; ++j) {
        int v = g_bsum[y][j];
        if (j < bx) boff += v;
        tot += v;
    }
    int i = bx * 1024 + threadIdx.x;
    const int* cnt = y ? g_cnt2 : g_cnt1;
    int* ptr = y ? g_ptr2 : g_ptr1;
    int* cur = y ? g_cur2 : g_cur1;
    int* src = y ? g_src2 : g_src1;
    float* val = y ? g_val2 : g_val1;
    int p = boff + g_locpre[y][i];
    ptr[i] = p; cur[i] = p;
    int cn = cnt[i], cr = (cn + 3) & ~3;
    for (int q = p + cn; q < p + cr; ++q) { src[q] = 0; val[q] = 0.f; }
    if (bx == 15 && threadIdx.x == 1023) ptr[NN] = tot;
    float* dg = y ? g_degc : g_degr;
    float d = dg[i];
    dg[i] = (d > 0.f) ? 1.f / d : 0.f;
}

// fused: one edge-list read fills both CSRs
__global__ void k_fill(const int* __restrict__ rows, const int* __restrict__ cols,
                       const float* __restrict__ adj) {
    int e = blockIdx.x * blockDim.x + threadIdx.x;
    if (e >= EE) return;
    int r = rows[e], c = cols[e];
    float a = adj[e];
    int p = atomicAdd(&g_cur1[c], 1);
    g_src1[p] = r;
    g_val1[p] = a * g_degr[r];
    int q = atomicAdd(&g_cur2[r], 1);
    g_src2[q] = c;
    g_val2[q] = a * g_degc[c];
}

// ---------------- SpMM (R3/R5-proven mainloop): warp = (dst node, 4 batches) ----------------
__device__ __forceinline__ void acc8(float2* acc, uint4 g, float v) {
    __half2* h = (__half2*)&g;
#pragma unroll
    for (int k = 0; k < 4; ++k) {
        float2 f = __half22float2(h[k]);
        acc[k].x = fmaf(v, f.x, acc[k].x);
        acc[k].y = fmaf(v, f.y, acc[k].y);
    }
}

// CHEB: do 2*acc - XM (XM streamed with __ldcs).
// STREAMST: output never gathered again (T2/T4) -> evict-first store.
template <bool CHEB, bool STREAMST>
__global__ void __launch_bounds__(256) k_spmm(
    const int* __restrict__ ptr, const int* __restrict__ srcs,
    const float* __restrict__ vals, const __half* __restrict__ X,
    const __half* __restrict__ XM, __half* __restrict__ T)
{
    int lane = threadIdx.x & 31;
    int n = blockIdx.x * 8 + (threadIdx.x >> 5);
    int quad = blockIdx.y;                               // batches [quad*4, quad*4+4)
    int sub = (quad * 4 + (lane >> 3)) * 8 + (lane & 7); // uint4 index within 4KB node block
    const uint4* __restrict__ Xb = (const uint4*)X;

    int p0 = ptr[n], p1 = ptr[n + 1];                    // segment length multiple of 4
    float2 acc[4] = {{0.f,0.f},{0.f,0.f},{0.f,0.f},{0.f,0.f}};

    for (int base = p0; base < p1; base += 32) {
        int idx = base + lane;
        int s = 0; float v = 0.f;
        if (idx < p1) { s = srcs[idx]; v = vals[idx]; }
        int cnt = min(32, p1 - base);                    // multiple of 4
        for (int j = 0; j < cnt; j += 4) {
            int s0 = __shfl_sync(0xffffffffu, s, j);
            int s1 = __shfl_sync(0xffffffffu, s, j + 1);
            int s2 = __shfl_sync(0xffffffffu, s, j + 2);
            int s3 = __shfl_sync(0xffffffffu, s, j + 3);
            float v0 = __shfl_sync(0xffffffffu, v, j);
            float v1 = __shfl_sync(0xffffffffu, v, j + 1);
            float v2 = __shfl_sync(0xffffffffu, v, j + 2);
            float v3 = __shfl_sync(0xffffffffu, v, j + 3);
            uint4 g0 = Xb[s0 * 256 + sub];
            uint4 g1 = Xb[s1 * 256 + sub];
            uint4 g2 = Xb[s2 * 256 + sub];
            uint4 g3 = Xb[s3 * 256 + sub];
            acc8(acc, g0, v0);
            acc8(acc, g1, v1);
            acc8(acc, g2, v2);
            acc8(acc, g3, v3);
        }
    }

    size_t o = (size_t)n * 256 + sub;                    // uint4 units
    if (CHEB) {
        uint4 mg = __ldcs((const uint4*)XM + o);         // streamed, evict-first
        __half2* mh = (__half2*)&mg;
#pragma unroll
        for (int k = 0; k < 4; ++k) {
            float2 f = __half22float2(mh[k]);
            acc[k].x = 2.f * acc[k].x - f.x;
            acc[k].y = 2.f * acc[k].y - f.y;
        }
    }
    uint4 r;
    __half2* rh = (__half2*)&r;
#pragma unroll
    for (int k = 0; k < 4; ++k) rh[k] = __floats2half2_rn(acc[k].x, acc[k].y);
    if (STREAMST) __stcs((uint4*)T + o, r);
    else          ((uint4*)T)[o] = r;
}

// ---------------- tensor-core projection (W convert fused into smem fill) ----------------
// 1024 blocks x 8 warps; each warp sweeps 4 consecutive 16-row tiles.
__global__ void __launch_bounds__(256) k_gemm_tc(
    const __half* __restrict__ Xh, const __half* __restrict__ T1,
    const __half* __restrict__ T2, const __half* __restrict__ T3,
    const __half* __restrict__ T4, const float* __restrict__ W,
    const float* __restrict__ bias, float* __restrict__ out)
{
    __shared__ __half Wsh[MM * DD * DD];        // 40 KB, loaded + converted ONCE per block
    __shared__ float  Bsh[16 * 64];
    int tid = threadIdx.x;
    int warp = tid >> 5;

    // Wsh[(m*64+k)*64+o] = half(W[(k*5+m)*64+o]) — float4-vectorized permute+convert
#pragma unroll
    for (int i = tid; i < MM * DD * DD / 4; i += 256) {
        int m  = i >> 10;           // i / 1024
        int k  = (i >> 4) & 63;
        int o4 = i & 15;
        float4 v = *(const float4*)(W + (size_t)(k * MM + m) * DD + o4 * 4);
        ((__half2*)Wsh)[(m * 64 + k) * 32 + o4 * 2]     = __floats2half2_rn(v.x, v.y);
        ((__half2*)Wsh)[(m * 64 + k) * 32 + o4 * 2 + 1] = __floats2half2_rn(v.z, v.w);
    }
#pragma unroll
    for (int i = tid; i < 16 * 64; i += 256) Bsh[i] = bias[i & 63];
    __syncthreads();

    const __half* bufs[5] = {Xh, T1, T2, T3, T4};

#pragma unroll
    for (int t = 0; t < 4; ++t) {
        int tile = (blockIdx.x * 8 + warp) * 4 + t;
        int r0 = tile * 16;                 // global A row
        int n  = r0 >> 5;
        int b0 = r0 & 31;                   // 0 or 16

        wmma::fragment<wmma::accumulator, 16, 16, 16, float> c[4];
#pragma unroll
        for (int j = 0; j < 4; ++j)
            wmma::load_matrix_sync(c[j], &Bsh[j * 16], 64, wmma::mem_row_major);

#pragma unroll
        for (int m = 0; m < 5; ++m) {
            const __half* A = bufs[m] + (size_t)r0 * DD;
#pragma unroll
            for (int kt = 0; kt < 4; ++kt) {
                wmma::fragment<wmma::matrix_a, 16, 16, 16, __half, wmma::row_major> a;
                wmma::load_matrix_sync(a, A + kt * 16, 64);
#pragma unroll
                for (int j = 0; j < 4; ++j) {
                    wmma::fragment<wmma::matrix_b, 16, 16, 16, __half, wmma::row_major> b;
                    wmma::load_matrix_sync(b, &Wsh[(m * 64 + kt * 16) * 64 + j * 16], 64);
                    wmma::mma_sync(c[j], a, b, c[j]);
                }
            }
        }
        float* ob = out + ((size_t)b0 * NN + n) * DD;
#pragma unroll
        for (int j = 0; j < 4; ++j)
            wmma::store_matrix_sync(ob + j * 16, c[j], NN * DD, wmma::mem_row_major);
    }
}

// ---------------- launch ----------------
extern "C" void kernel_launch(void* const* d_in, const int* in_sizes, int n_in,
                              void* d_out, int out_size)
{
    const float* inputs  = (const float*)d_in[0];   // [B, N, D]
    const float* adj     = (const float*)d_in[1];   // [E]
    const int*   rows    = (const int*)d_in[2];     // [E]
    const int*   cols    = (const int*)d_in[3];     // [E]
    const float* weights = (const float*)d_in[4];   // [D*M, OUT]
    const float* biases  = (const float*)d_in[5];   // [1, OUT]
    float* out = (float*)d_out;                     // [B, N, OUT]
    (void)in_sizes; (void)n_in; (void)out_size;

    void *pP1, *pP2, *pS1, *pS2, *pV1, *pV2, *pX, *pT1, *pT2, *pT3, *pT4;
    cudaGetSymbolAddress(&pP1, g_ptr1);
    cudaGetSymbolAddress(&pP2, g_ptr2);
    cudaGetSymbolAddress(&pS1, g_src1);
    cudaGetSymbolAddress(&pS2, g_src2);
    cudaGetSymbolAddress(&pV1, g_val1);
    cudaGetSymbolAddress(&pV2, g_val2);
    cudaGetSymbolAddress(&pX,  g_Xh);
    cudaGetSymbolAddress(&pT1, g_T1);
    cudaGetSymbolAddress(&pT2, g_T2);
    cudaGetSymbolAddress(&pT3, g_T3);
    cudaGetSymbolAddress(&pT4, g_T4);

    k_zero<<<(NN + 255) / 256, 256>>>();
    // degree atomics + FULL X convert, fused (grid sized for BOTH halves)
    k_pre<<<EDGE_BLOCKS + CVT_BLOCKS, 256>>>(rows, cols, adj, inputs);
    k_scanA<<<dim3(16, 2), 1024>>>();
    k_scanC<<<dim3(16, 2), 1024>>>();
    k_fill<<<(EE + 255) / 256, 256>>>(rows, cols, adj);

    dim3 sg(NN / 8, 8);
    // T1 = S1 @ X0           (T1 gathered by later passes -> cached store)
    k_spmm<false, false><<<sg, 256>>>((const int*)pP1, (const int*)pS1, (const float*)pV1,
                                      (const __half*)pX, nullptr, (__half*)pT1);
    // T2 = 2*S1 @ T1 - X0    (T2 only read by GEMM -> streaming store)
    k_spmm<true, true><<<sg, 256>>>((const int*)pP1, (const int*)pS1, (const float*)pV1,
                                    (const __half*)pT1, (const __half*)pX, (__half*)pT2);
    // T3 = S2 @ T1           (T3 gathered by pass4 -> cached store)
    k_spmm<false, false><<<sg, 256>>>((const int*)pP2, (const int*)pS2, (const float*)pV2,
                                      (const __half*)pT1, nullptr, (__half*)pT3);
    // T4 = 2*S2 @ T3 - T1    (T4 only read by GEMM -> streaming store)
    k_spmm<true, true><<<sg, 256>>>((const int*)pP2, (const int*)pS2, (const float*)pV2,
                                    (const __half*)pT3, (const __half*)pT1, (__half*)pT4);

    k_gemm_tc<<<(BB * NN) / (4 * 8 * 16), 256>>>((const __half*)pX, (const __half*)pT1,
                                                 (const __half*)pT2, (const __half*)pT3,
                                                 (const __half*)pT4, weights, biases, out);
}

// round 10
// speedup vs baseline: 1.1141x; 1.0028x over previous
#include <cuda_runtime.h>
#include <cuda_fp16.h>
#include <mma.h>
#include <cstdint>

#define NN 16384
#define EE 524288
#define EPAD (EE + 4 * NN)
#define BB 32
#define DD 64
#define MM 5

using namespace nvcuda;

// ---------------- device scratch (static, allocation-free) ----------------
// fp16 operand buffers, TRANSPOSED layout: buf[(n*32 + b)*64 + d]
__device__ __half g_Xh[(size_t)BB * NN * DD];
__device__ __half g_T1[(size_t)BB * NN * DD];
__device__ __half g_T2[(size_t)BB * NN * DD];
__device__ __half g_T3[(size_t)BB * NN * DD];
__device__ __half g_T4[(size_t)BB * NN * DD];

__device__ float g_degr[NN];
__device__ float g_degc[NN];
__device__ int   g_cnt1[NN], g_cnt2[NN];
__device__ int   g_ptr1[NN + 1], g_ptr2[NN + 1];
__device__ int   g_cur1[NN], g_cur2[NN];
__device__ int   g_src1[EPAD], g_src2[EPAD];
__device__ float g_val1[EPAD], g_val2[EPAD];

// scan intermediates
__device__ int g_locpre[2][NN];
__device__ int g_bsum[2][16];

#define CVT_BLOCKS 65536   // BB*NN*DD/2 half2 elems / 256 threads
#define EDGE_BLOCKS 2048   // EE / 256

// ---------------- init ----------------
__global__ void k_zero() {
    int i = blockIdx.x * blockDim.x + threadIdx.x;
    if (i < NN) {
        g_degr[i] = 0.f; g_degc[i] = 0.f;
        g_cnt1[i] = 0;   g_cnt2[i] = 0;
    }
}

// fused: blocks [0,EDGE_BLOCKS) = degree/histogram atomics;
//        blocks [EDGE_BLOCKS, EDGE_BLOCKS+CVT_BLOCKS) = X transpose-convert.
// inputs [b][n][d] fp32 -> g_Xh [(n*32+b)*64+d] fp16 (transpose b<->n)
__global__ void k_pre(const int* __restrict__ rows, const int* __restrict__ cols,
                      const float* __restrict__ adj, const float* __restrict__ X) {
    int bx = blockIdx.x;
    if (bx < EDGE_BLOCKS) {
        int e = bx * 256 + threadIdx.x;
        if (e >= EE) return;
        int r = rows[e], c = cols[e];
        float a = adj[e];
        atomicAdd(&g_degr[r], a);
        atomicAdd(&g_degc[c], a);
        atomicAdd(&g_cnt1[c], 1);   // S1 scatters to cols
        atomicAdd(&g_cnt2[r], 1);   // S2 scatters to rows
    } else {
        int i = (bx - EDGE_BLOCKS) * 256 + threadIdx.x;   // half2 index in TARGET
        if (i >= BB * NN * (DD / 2)) return;
        int dh = i & 31;
        int b  = (i >> 5) & 31;
        int n  = i >> 10;
        float2 v = ((const float2*)X)[((size_t)b * NN + n) * 32 + dh];
        ((__half2*)g_Xh)[i] = __floats2half2_rn(v.x, v.y);
    }
}

// ---------------- parallel scan (both CSRs via blockIdx.y) ----------------
// Phase A: per-block (1024 counts) exclusive scan of padded counts
__global__ void __launch_bounds__(1024) k_scanA() {
    int y = blockIdx.y;
    const int* cnt = y ? g_cnt2 : g_cnt1;
    int i = blockIdx.x * 1024 + threadIdx.x;
    int c = (cnt[i] + 3) & ~3;
    int lane = threadIdx.x & 31, w = threadIdx.x >> 5;
    int x = c;
#pragma unroll
    for (int o = 1; o < 32; o <<= 1) {
        int t = __shfl_up_sync(0xffffffffu, x, o);
        if (lane >= o) x += t;
    }
    __shared__ int wsum[32];
    if (lane == 31) wsum[w] = x;
    __syncthreads();
    if (w == 0) {
        int t = wsum[lane];
#pragma unroll
        for (int o = 1; o < 32; o <<= 1) {
            int u = __shfl_up_sync(0xffffffffu, t, o);
            if (lane >= o) t += u;
        }
        wsum[lane] = t;
    }
    __syncthreads();
    int pre = x - c + (w ? wsum[w - 1] : 0);
    g_locpre[y][i] = pre;
    if (threadIdx.x == 1023) g_bsum[y][blockIdx.x] = pre + c;
}

// Phase C (with inlined 16-partial scan): finalize ptr/cur, zero pads, invert degrees
__global__ void __launch_bounds__(1024) k_scanC() {
    int y = blockIdx.y;
    int bx = blockIdx.x;
    int boff = 0, tot = 0;
#pragma unroll
    for (int j = 0; j < 16; ++j) {
        int v = g_bsum[y][j];
        if (j < bx) boff += v;
        tot += v;
    }
    int i = bx * 1024 + threadIdx.x;
    const int* cnt = y ? g_cnt2 : g_cnt1;
    int* ptr = y ? g_ptr2 : g_ptr1;
    int* cur = y ? g_cur2 : g_cur1;
    int* src = y ? g_src2 : g_src1;
    float* val = y ? g_val2 : g_val1;
    int p = boff + g_locpre[y][i];
    ptr[i] = p; cur[i] = p;
    int cn = cnt[i], cr = (cn + 3) & ~3;
    for (int q = p + cn; q < p + cr; ++q) { src[q] = 0; val[q] = 0.f; }
    if (bx == 15 && threadIdx.x == 1023) ptr[NN] = tot;
    float* dg = y ? g_degc : g_degr;
    float d = dg[i];
    dg[i] = (d > 0.f) ? 1.f / d : 0.f;
}

// fused: one edge-list read fills both CSRs
__global__ void k_fill(const int* __restrict__ rows, const int* __restrict__ cols,
                       const float* __restrict__ adj) {
    int e = blockIdx.x * blockDim.x + threadIdx.x;
    if (e >= EE) return;
    int r = rows[e], c = cols[e];
    float a = adj[e];
    int p = atomicAdd(&g_cur1[c], 1);
    g_src1[p] = r;
    g_val1[p] = a * g_degr[r];
    int q = atomicAdd(&g_cur2[r], 1);
    g_src2[q] = c;
    g_val2[q] = a * g_degc[c];
}

// ---------------- SpMM (R3/R5-proven mainloop): warp = (dst node, 4 batches) ----------------
__device__ __forceinline__ void acc8(float2* acc, uint4 g, float v) {
    __half2* h = (__half2*)&g;
#pragma unroll
    for (int k = 0; k < 4; ++k) {
        float2 f = __half22float2(h[k]);
        acc[k].x = fmaf(v, f.x, acc[k].x);
        acc[k].y = fmaf(v, f.y, acc[k].y);
    }
}

// shared mainloop: accumulates 4-batch slice for dst n over [p0,p1)
__device__ __forceinline__ void spmm_body(
    const int* __restrict__ srcs, const float* __restrict__ vals,
    const uint4* __restrict__ Xb, int p0, int p1, int lane, int sub, float2* acc)
{
    for (int base = p0; base < p1; base += 32) {
        int idx = base + lane;
        int s = 0; float v = 0.f;
        if (idx < p1) { s = srcs[idx]; v = vals[idx]; }
        int cnt = min(32, p1 - base);                    // multiple of 4
        for (int j = 0; j < cnt; j += 4) {
            int s0 = __shfl_sync(0xffffffffu, s, j);
            int s1 = __shfl_sync(0xffffffffu, s, j + 1);
            int s2 = __shfl_sync(0xffffffffu, s, j + 2);
            int s3 = __shfl_sync(0xffffffffu, s, j + 3);
            float v0 = __shfl_sync(0xffffffffu, v, j);
            float v1 = __shfl_sync(0xffffffffu, v, j + 1);
            float v2 = __shfl_sync(0xffffffffu, v, j + 2);
            float v3 = __shfl_sync(0xffffffffu, v, j + 3);
            uint4 g0 = Xb[s0 * 256 + sub];
            uint4 g1 = Xb[s1 * 256 + sub];
            uint4 g2 = Xb[s2 * 256 + sub];
            uint4 g3 = Xb[s3 * 256 + sub];
            acc8(acc, g0, v0);
            acc8(acc, g1, v1);
            acc8(acc, g2, v2);
            acc8(acc, g3, v3);
        }
    }
}

template <bool CHEB, bool STREAMST>
__global__ void __launch_bounds__(256) k_spmm(
    const int* __restrict__ ptr, const int* __restrict__ srcs,
    const float* __restrict__ vals, const __half* __restrict__ X,
    const __half* __restrict__ XM, __half* __restrict__ T)
{
    int lane = threadIdx.x & 31;
    int n = blockIdx.x * 8 + (threadIdx.x >> 5);
    int quad = blockIdx.y;                               // batches [quad*4, quad*4+4)
    int sub = (quad * 4 + (lane >> 3)) * 8 + (lane & 7); // uint4 index within 4KB node block

    int p0 = ptr[n], p1 = ptr[n + 1];                    // segment length multiple of 4
    float2 acc[4] = {{0.f,0.f},{0.f,0.f},{0.f,0.f},{0.f,0.f}};
    spmm_body(srcs, vals, (const uint4*)X, p0, p1, lane, sub, acc);

    size_t o = (size_t)n * 256 + sub;                    // uint4 units
    if (CHEB) {
        uint4 mg = __ldcs((const uint4*)XM + o);         // streamed, evict-first
        __half2* mh = (__half2*)&mg;
#pragma unroll
        for (int k = 0; k < 4; ++k) {
            float2 f = __half22float2(mh[k]);
            acc[k].x = 2.f * acc[k].x - f.x;
            acc[k].y = 2.f * acc[k].y - f.y;
        }
    }
    uint4 r;
    __half2* rh = (__half2*)&r;
#pragma unroll
    for (int k = 0; k < 4; ++k) rh[k] = __floats2half2_rn(acc[k].x, acc[k].y);
    if (STREAMST) __stcs((uint4*)T + o, r);
    else          ((uint4*)T)[o] = r;
}

// fused pass2 (z=0: T2 = 2*S1@T1 - Xh, streaming store) and
//       pass3 (z=1: T3 = S2@T1, cached store) — both gather T1 only.
__global__ void __launch_bounds__(256) k_spmm23(
    const int* __restrict__ ptr1, const int* __restrict__ src1, const float* __restrict__ val1,
    const int* __restrict__ ptr2, const int* __restrict__ src2, const float* __restrict__ val2,
    const __half* __restrict__ T1, const __half* __restrict__ Xh,
    __half* __restrict__ T2, __half* __restrict__ T3)
{
    int lane = threadIdx.x & 31;
    int n = blockIdx.x * 8 + (threadIdx.x >> 5);
    int quad = blockIdx.y;
    int sub = (quad * 4 + (lane >> 3)) * 8 + (lane & 7);
    bool pass3 = (blockIdx.z != 0);

    const int* ptr = pass3 ? ptr2 : ptr1;
    const int* srcs = pass3 ? src2 : src1;
    const float* vals = pass3 ? val2 : val1;

    int p0 = ptr[n], p1 = ptr[n + 1];
    float2 acc[4] = {{0.f,0.f},{0.f,0.f},{0.f,0.f},{0.f,0.f}};
    spmm_body(srcs, vals, (const uint4*)T1, p0, p1, lane, sub, acc);

    size_t o = (size_t)n * 256 + sub;
    if (!pass3) {   // Chebyshev epilogue + streaming store to T2
        uint4 mg = __ldcs((const uint4*)Xh + o);
        __half2* mh = (__half2*)&mg;
#pragma unroll
        for (int k = 0; k < 4; ++k) {
            float2 f = __half22float2(mh[k]);
            acc[k].x = 2.f * acc[k].x - f.x;
            acc[k].y = 2.f * acc[k].y - f.y;
        }
        uint4 r;
        __half2* rh = (__half2*)&r;
#pragma unroll
        for (int k = 0; k < 4; ++k) rh[k] = __floats2half2_rn(acc[k].x, acc[k].y);
        __stcs((uint4*)T2 + o, r);
    } else {        // plain store to T3 (gathered by pass4 -> cached)
        uint4 r;
        __half2* rh = (__half2*)&r;
#pragma unroll
        for (int k = 0; k < 4; ++k) rh[k] = __floats2half2_rn(acc[k].x, acc[k].y);
        ((uint4*)T3)[o] = r;
    }
}

// ---------------- tensor-core projection (W convert fused into smem fill) ----------------
// 1024 blocks x 8 warps; each warp sweeps 4 consecutive 16-row tiles.
__global__ void __launch_bounds__(256) k_gemm_tc(
    const __half* __restrict__ Xh, const __half* __restrict__ T1,
    const __half* __restrict__ T2, const __half* __restrict__ T3,
    const __half* __restrict__ T4, const float* __restrict__ W,
    const float* __restrict__ bias, float* __restrict__ out)
{
    __shared__ __half Wsh[MM * DD * DD];        // 40 KB, loaded + converted ONCE per block
    __shared__ float  Bsh[16 * 64];
    int tid = threadIdx.x;
    int warp = tid >> 5;

    // Wsh[(m*64+k)*64+o] = half(W[(k*5+m)*64+o]) — float4-vectorized permute+convert
#pragma unroll
    for (int i = tid; i < MM * DD * DD / 4; i += 256) {
        int m  = i >> 10;           // i / 1024
        int k  = (i >> 4) & 63;
        int o4 = i & 15;
        float4 v = *(const float4*)(W + (size_t)(k * MM + m) * DD + o4 * 4);
        ((__half2*)Wsh)[(m * 64 + k) * 32 + o4 * 2]     = __floats2half2_rn(v.x, v.y);
        ((__half2*)Wsh)[(m * 64 + k) * 32 + o4 * 2 + 1] = __floats2half2_rn(v.z, v.w);
    }
#pragma unroll
    for (int i = tid; i < 16 * 64; i += 256) Bsh[i] = bias[i & 63];
    __syncthreads();

    const __half* bufs[5] = {Xh, T1, T2, T3, T4};

#pragma unroll
    for (int t = 0; t < 4; ++t) {
        int tile = (blockIdx.x * 8 + warp) * 4 + t;
        int r0 = tile * 16;                 // global A row
        int n  = r0 >> 5;
        int b0 = r0 & 31;                   // 0 or 16

        wmma::fragment<wmma::accumulator, 16, 16, 16, float> c[4];
#pragma unroll
        for (int j = 0; j < 4; ++j)
            wmma::load_matrix_sync(c[j], &Bsh[j * 16], 64, wmma::mem_row_major);

#pragma unroll
        for (int m = 0; m < 5; ++m) {
            const __half* A = bufs[m] + (size_t)r0 * DD;
#pragma unroll
            for (int kt = 0; kt < 4; ++kt) {
                wmma::fragment<wmma::matrix_a, 16, 16, 16, __half, wmma::row_major> a;
                wmma::load_matrix_sync(a, A + kt * 16, 64);
#pragma unroll
                for (int j = 0; j < 4; ++j) {
                    wmma::fragment<wmma::matrix_b, 16, 16, 16, __half, wmma::row_major> b;
                    wmma::load_matrix_sync(b, &Wsh[(m * 64 + kt * 16) * 64 + j * 16], 64);
                    wmma::mma_sync(c[j], a, b, c[j]);
                }
            }
        }
        float* ob = out + ((size_t)b0 * NN + n) * DD;
#pragma unroll
        for (int j = 0; j < 4; ++j)
            wmma::store_matrix_sync(ob + j * 16, c[j], NN * DD, wmma::mem_row_major);
    }
}

// ---------------- launch ----------------
extern "C" void kernel_launch(void* const* d_in, const int* in_sizes, int n_in,
                              void* d_out, int out_size)
{
    const float* inputs  = (const float*)d_in[0];   // [B, N, D]
    const float* adj     = (const float*)d_in[1];   // [E]
    const int*   rows    = (const int*)d_in[2];     // [E]
    const int*   cols    = (const int*)d_in[3];     // [E]
    const float* weights = (const float*)d_in[4];   // [D*M, OUT]
    const float* biases  = (const float*)d_in[5];   // [1, OUT]
    float* out = (float*)d_out;                     // [B, N, OUT]
    (void)in_sizes; (void)n_in; (void)out_size;

    void *pP1, *pP2, *pS1, *pS2, *pV1, *pV2, *pX, *pT1, *pT2, *pT3, *pT4;
    cudaGetSymbolAddress(&pP1, g_ptr1);
    cudaGetSymbolAddress(&pP2, g_ptr2);
    cudaGetSymbolAddress(&pS1, g_src1);
    cudaGetSymbolAddress(&pS2, g_src2);
    cudaGetSymbolAddress(&pV1, g_val1);
    cudaGetSymbolAddress(&pV2, g_val2);
    cudaGetSymbolAddress(&pX,  g_Xh);
    cudaGetSymbolAddress(&pT1, g_T1);
    cudaGetSymbolAddress(&pT2, g_T2);
    cudaGetSymbolAddress(&pT3, g_T3);
    cudaGetSymbolAddress(&pT4, g_T4);

    k_zero<<<(NN + 255) / 256, 256>>>();
    // degree atomics + FULL X convert, fused
    k_pre<<<EDGE_BLOCKS + CVT_BLOCKS, 256>>>(rows, cols, adj, inputs);
    k_scanA<<<dim3(16, 2), 1024>>>();
    k_scanC<<<dim3(16, 2), 1024>>>();
    k_fill<<<(EE + 255) / 256, 256>>>(rows, cols, adj);

    dim3 sg(NN / 8, 8);
    // pass1: T1 = S1 @ X0    (T1 gathered by later passes -> cached store)
    k_spmm<false, false><<<sg, 256>>>((const int*)pP1, (const int*)pS1, (const float*)pV1,
                                      (const __half*)pX, nullptr, (__half*)pT1);
    // pass2 ∥ pass3 fused: T2 = 2*S1@T1 - X0 ; T3 = S2@T1
    dim3 sg23(NN / 8, 8, 2);
    k_spmm23<<<sg23, 256>>>((const int*)pP1, (const int*)pS1, (const float*)pV1,
                            (const int*)pP2, (const int*)pS2, (const float*)pV2,
                            (const __half*)pT1, (const __half*)pX,
                            (__half*)pT2, (__half*)pT3);
    // pass4: T4 = 2*S2 @ T3 - T1   (T4 only read by GEMM -> streaming store)
    k_spmm<true, true><<<sg, 256>>>((const int*)pP2, (const int*)pS2, (const float*)pV2,
                                    (const __half*)pT3, (const __half*)pT1, (__half*)pT4);

    k_gemm_tc<<<(BB * NN) / (4 * 8 * 16), 256>>>((const __half*)pX, (const __half*)pT1,
                                                 (const __half*)pT2, (const __half*)pT3,
                                                 (const __half*)pT4, weights, biases, out);
}

// round 11
// speedup vs baseline: 1.1151x; 1.0009x over previous
#include <cuda_runtime.h>
#include <cuda_fp16.h>
#include <mma.h>
#include <cstdint>

#define NN 16384
#define EE 524288
#define EPAD (EE + 4 * NN)
#define BB 32
#define DD 64
#define MM 5

using namespace nvcuda;

// ---------------- device scratch (static, allocation-free) ----------------
// fp16 operand buffers, TRANSPOSED layout: buf[(n*32 + b)*64 + d]
__device__ __half g_Xh[(size_t)BB * NN * DD];
__device__ __half g_T1[(size_t)BB * NN * DD];
__device__ __half g_T2[(size_t)BB * NN * DD];
__device__ __half g_T3[(size_t)BB * NN * DD];
__device__ __half g_T4[(size_t)BB * NN * DD];

__device__ float g_degr[NN];
__device__ float g_degc[NN];
__device__ int   g_cnt1[NN], g_cnt2[NN];
__device__ int   g_ptr1[NN + 1], g_ptr2[NN + 1];
__device__ int   g_cur1[NN], g_cur2[NN];
__device__ int   g_src1[EPAD], g_src2[EPAD];
__device__ float g_val1[EPAD], g_val2[EPAD];

#define CVT_BLOCKS 65536   // BB*NN*DD/2 half2 elems / 256 threads
#define EDGE_BLOCKS 2048   // EE / 256

// ---------------- init ----------------
__global__ void k_zero() {
    int i = blockIdx.x * blockDim.x + threadIdx.x;
    if (i < NN) {
        g_degr[i] = 0.f; g_degc[i] = 0.f;
        g_cnt1[i] = 0;   g_cnt2[i] = 0;
    }
}

// fused: blocks [0,EDGE_BLOCKS) = degree/histogram atomics;
//        blocks [EDGE_BLOCKS, EDGE_BLOCKS+CVT_BLOCKS) = X transpose-convert.
// inputs [b][n][d] fp32 -> g_Xh [(n*32+b)*64+d] fp16 (transpose b<->n)
__global__ void k_pre(const int* __restrict__ rows, const int* __restrict__ cols,
                      const float* __restrict__ adj, const float* __restrict__ X) {
    int bx = blockIdx.x;
    if (bx < EDGE_BLOCKS) {
        int e = bx * 256 + threadIdx.x;
        if (e >= EE) return;
        int r = rows[e], c = cols[e];
        float a = adj[e];
        atomicAdd(&g_degr[r], a);
        atomicAdd(&g_degc[c], a);
        atomicAdd(&g_cnt1[c], 1);   // S1 scatters to cols
        atomicAdd(&g_cnt2[r], 1);   // S2 scatters to rows
    } else {
        int i = (bx - EDGE_BLOCKS) * 256 + threadIdx.x;   // half2 index in TARGET
        if (i >= BB * NN * (DD / 2)) return;
        int dh = i & 31;
        int b  = (i >> 5) & 31;
        int n  = i >> 10;
        float2 v = ((const float2*)X)[((size_t)b * NN + n) * 32 + dh];
        ((__half2*)g_Xh)[i] = __floats2half2_rn(v.x, v.y);
    }
}

// ---------------- single-kernel scan (both CSRs via blockIdx.y) ----------------
// Each block: (1) intra-block shuffle scan of padded counts, (2) cooperative sum of
// all padded counts BEFORE this block = global offset, (3) write ptr/cur, zero pads,
// invert degrees, write ptr[NN].
__global__ void __launch_bounds__(1024) k_scan() {
    int y = blockIdx.y;
    int bx = blockIdx.x;
    const int* cnt = y ? g_cnt2 : g_cnt1;
    int i = bx * 1024 + threadIdx.x;
    int lane = threadIdx.x & 31, w = threadIdx.x >> 5;
    __shared__ int sh[32];

    // (1) intra-block exclusive scan of padded counts
    int c = (cnt[i] + 3) & ~3;
    int x = c;
#pragma unroll
    for (int o = 1; o < 32; o <<= 1) {
        int t = __shfl_up_sync(0xffffffffu, x, o);
        if (lane >= o) x += t;
    }
    if (lane == 31) sh[w] = x;
    __syncthreads();
    if (w == 0) {
        int t = sh[lane];
#pragma unroll
        for (int o = 1; o < 32; o <<= 1) {
            int u = __shfl_up_sync(0xffffffffu, t, o);
            if (lane >= o) t += u;
        }
        sh[lane] = t;
    }
    __syncthreads();
    int pre = x - c + (w ? sh[w - 1] : 0);   // exclusive prefix within block
    __syncthreads();                          // done with sh as scan buffer

    // (2) global block offset: sum padded counts in [0, bx*1024)
    int part = 0;
    for (int j = threadIdx.x; j < bx * 1024; j += 1024)
        part += (cnt[j] + 3) & ~3;
#pragma unroll
    for (int o = 16; o > 0; o >>= 1)
        part += __shfl_down_sync(0xffffffffu, part, o);
    if (lane == 0) sh[w] = part;
    __syncthreads();
    if (w == 0) {
        int t = sh[lane];
#pragma unroll
        for (int o = 16; o > 0; o >>= 1)
            t += __shfl_down_sync(0xffffffffu, t, o);
        if (lane == 0) sh[0] = t;
    }
    __syncthreads();
    int boff = sh[0];

    // (3) finalize
    int* ptr = y ? g_ptr2 : g_ptr1;
    int* cur = y ? g_cur2 : g_cur1;
    int* src = y ? g_src2 : g_src1;
    float* val = y ? g_val2 : g_val1;
    int p = boff + pre;
    ptr[i] = p; cur[i] = p;
    int cn = cnt[i], cr = (cn + 3) & ~3;
    for (int q = p + cn; q < p + cr; ++q) { src[q] = 0; val[q] = 0.f; }
    if (bx == 15 && threadIdx.x == 1023) ptr[NN] = p + cr;
    float* dg = y ? g_degc : g_degr;
    float d = dg[i];
    dg[i] = (d > 0.f) ? 1.f / d : 0.f;
}

// fused: one edge-list read fills both CSRs
__global__ void k_fill(const int* __restrict__ rows, const int* __restrict__ cols,
                       const float* __restrict__ adj) {
    int e = blockIdx.x * blockDim.x + threadIdx.x;
    if (e >= EE) return;
    int r = rows[e], c = cols[e];
    float a = adj[e];
    int p = atomicAdd(&g_cur1[c], 1);
    g_src1[p] = r;
    g_val1[p] = a * g_degr[r];
    int q = atomicAdd(&g_cur2[r], 1);
    g_src2[q] = c;
    g_val2[q] = a * g_degc[c];
}

// ---------------- SpMM (proven mainloop): warp = (dst node, 4 batches) ----------------
__device__ __forceinline__ void acc8(float2* acc, uint4 g, float v) {
    __half2* h = (__half2*)&g;
#pragma unroll
    for (int k = 0; k < 4; ++k) {
        float2 f = __half22float2(h[k]);
        acc[k].x = fmaf(v, f.x, acc[k].x);
        acc[k].y = fmaf(v, f.y, acc[k].y);
    }
}

// shared mainloop: accumulates 4-batch slice for dst n over [p0,p1)
__device__ __forceinline__ void spmm_body(
    const int* __restrict__ srcs, const float* __restrict__ vals,
    const uint4* __restrict__ Xb, int p0, int p1, int lane, int sub, float2* acc)
{
    for (int base = p0; base < p1; base += 32) {
        int idx = base + lane;
        int s = 0; float v = 0.f;
        if (idx < p1) { s = srcs[idx]; v = vals[idx]; }
        int cnt = min(32, p1 - base);                    // multiple of 4
        for (int j = 0; j < cnt; j += 4) {
            int s0 = __shfl_sync(0xffffffffu, s, j);
            int s1 = __shfl_sync(0xffffffffu, s, j + 1);
            int s2 = __shfl_sync(0xffffffffu, s, j + 2);
            int s3 = __shfl_sync(0xffffffffu, s, j + 3);
            float v0 = __shfl_sync(0xffffffffu, v, j);
            float v1 = __shfl_sync(0xffffffffu, v, j + 1);
            float v2 = __shfl_sync(0xffffffffu, v, j + 2);
            float v3 = __shfl_sync(0xffffffffu, v, j + 3);
            uint4 g0 = Xb[s0 * 256 + sub];
            uint4 g1 = Xb[s1 * 256 + sub];
            uint4 g2 = Xb[s2 * 256 + sub];
            uint4 g3 = Xb[s3 * 256 + sub];
            acc8(acc, g0, v0);
            acc8(acc, g1, v1);
            acc8(acc, g2, v2);
            acc8(acc, g3, v3);
        }
    }
}

template <bool CHEB, bool STREAMST>
__global__ void __launch_bounds__(256) k_spmm(
    const int* __restrict__ ptr, const int* __restrict__ srcs,
    const float* __restrict__ vals, const __half* __restrict__ X,
    const __half* __restrict__ XM, __half* __restrict__ T)
{
    int lane = threadIdx.x & 31;
    int n = blockIdx.x * 8 + (threadIdx.x >> 5);
    int quad = blockIdx.y;                               // batches [quad*4, quad*4+4)
    int sub = (quad * 4 + (lane >> 3)) * 8 + (lane & 7); // uint4 index within 4KB node block

    int p0 = ptr[n], p1 = ptr[n + 1];                    // segment length multiple of 4
    float2 acc[4] = {{0.f,0.f},{0.f,0.f},{0.f,0.f},{0.f,0.f}};
    spmm_body(srcs, vals, (const uint4*)X, p0, p1, lane, sub, acc);

    size_t o = (size_t)n * 256 + sub;                    // uint4 units
    if (CHEB) {
        uint4 mg = __ldcs((const uint4*)XM + o);         // streamed, evict-first
        __half2* mh = (__half2*)&mg;
#pragma unroll
        for (int k = 0; k < 4; ++k) {
            float2 f = __half22float2(mh[k]);
            acc[k].x = 2.f * acc[k].x - f.x;
            acc[k].y = 2.f * acc[k].y - f.y;
        }
    }
    uint4 r;
    __half2* rh = (__half2*)&r;
#pragma unroll
    for (int k = 0; k < 4; ++k) rh[k] = __floats2half2_rn(acc[k].x, acc[k].y);
    if (STREAMST) __stcs((uint4*)T + o, r);
    else          ((uint4*)T)[o] = r;
}

// fused pass2 (z=0: T2 = 2*S1@T1 - Xh, streaming store) and
//       pass3 (z=1: T3 = S2@T1, cached store) — both gather T1 only.
__global__ void __launch_bounds__(256) k_spmm23(
    const int* __restrict__ ptr1, const int* __restrict__ src1, const float* __restrict__ val1,
    const int* __restrict__ ptr2, const int* __restrict__ src2, const float* __restrict__ val2,
    const __half* __restrict__ T1, const __half* __restrict__ Xh,
    __half* __restrict__ T2, __half* __restrict__ T3)
{
    int lane = threadIdx.x & 31;
    int n = blockIdx.x * 8 + (threadIdx.x >> 5);
    int quad = blockIdx.y;
    int sub = (quad * 4 + (lane >> 3)) * 8 + (lane & 7);
    bool pass3 = (blockIdx.z != 0);

    const int* ptr = pass3 ? ptr2 : ptr1;
    const int* srcs = pass3 ? src2 : src1;
    const float* vals = pass3 ? val2 : val1;

    int p0 = ptr[n], p1 = ptr[n + 1];
    float2 acc[4] = {{0.f,0.f},{0.f,0.f},{0.f,0.f},{0.f,0.f}};
    spmm_body(srcs, vals, (const uint4*)T1, p0, p1, lane, sub, acc);

    size_t o = (size_t)n * 256 + sub;
    if (!pass3) {   // Chebyshev epilogue + streaming store to T2
        uint4 mg = __ldcs((const uint4*)Xh + o);
        __half2* mh = (__half2*)&mg;
#pragma unroll
        for (int k = 0; k < 4; ++k) {
            float2 f = __half22float2(mh[k]);
            acc[k].x = 2.f * acc[k].x - f.x;
            acc[k].y = 2.f * acc[k].y - f.y;
        }
        uint4 r;
        __half2* rh = (__half2*)&r;
#pragma unroll
        for (int k = 0; k < 4; ++k) rh[k] = __floats2half2_rn(acc[k].x, acc[k].y);
        __stcs((uint4*)T2 + o, r);
    } else {        // plain store to T3 (gathered by pass4 -> cached)
        uint4 r;
        __half2* rh = (__half2*)&r;
#pragma unroll
        for (int k = 0; k < 4; ++k) rh[k] = __floats2half2_rn(acc[k].x, acc[k].y);
        ((uint4*)T3)[o] = r;
    }
}

// ---------------- tensor-core projection (W convert fused into smem fill) ----------------
// 1024 blocks x 8 warps; each warp sweeps 4 consecutive 16-row tiles.
__global__ void __launch_bounds__(256) k_gemm_tc(
    const __half* __restrict__ Xh, const __half* __restrict__ T1,
    const __half* __restrict__ T2, const __half* __restrict__ T3,
    const __half* __restrict__ T4, const float* __restrict__ W,
    const float* __restrict__ bias, float* __restrict__ out)
{
    __shared__ __half Wsh[MM * DD * DD];        // 40 KB, loaded + converted ONCE per block
    __shared__ float  Bsh[16 * 64];
    int tid = threadIdx.x;
    int warp = tid >> 5;

    // Wsh[(m*64+k)*64+o] = half(W[(k*5+m)*64+o]) — float4-vectorized permute+convert
#pragma unroll
    for (int i = tid; i < MM * DD * DD / 4; i += 256) {
        int m  = i >> 10;           // i / 1024
        int k  = (i >> 4) & 63;
        int o4 = i & 15;
        float4 v = *(const float4*)(W + (size_t)(k * MM + m) * DD + o4 * 4);
        ((__half2*)Wsh)[(m * 64 + k) * 32 + o4 * 2]     = __floats2half2_rn(v.x, v.y);
        ((__half2*)Wsh)[(m * 64 + k) * 32 + o4 * 2 + 1] = __floats2half2_rn(v.z, v.w);
    }
#pragma unroll
    for (int i = tid; i < 16 * 64; i += 256) Bsh[i] = bias[i & 63];
    __syncthreads();

    const __half* bufs[5] = {Xh, T1, T2, T3, T4};

#pragma unroll
    for (int t = 0; t < 4; ++t) {
        int tile = (blockIdx.x * 8 + warp) * 4 + t;
        int r0 = tile * 16;                 // global A row
        int n  = r0 >> 5;
        int b0 = r0 & 31;                   // 0 or 16

        wmma::fragment<wmma::accumulator, 16, 16, 16, float> c[4];
#pragma unroll
        for (int j = 0; j < 4; ++j)
            wmma::load_matrix_sync(c[j], &Bsh[j * 16], 64, wmma::mem_row_major);

#pragma unroll
        for (int m = 0; m < 5; ++m) {
            const __half* A = bufs[m] + (size_t)r0 * DD;
#pragma unroll
            for (int kt = 0; kt < 4; ++kt) {
                wmma::fragment<wmma::matrix_a, 16, 16, 16, __half, wmma::row_major> a;
                wmma::load_matrix_sync(a, A + kt * 16, 64);
#pragma unroll
                for (int j = 0; j < 4; ++j) {
                    wmma::fragment<wmma::matrix_b, 16, 16, 16, __half, wmma::row_major> b;
                    wmma::load_matrix_sync(b, &Wsh[(m * 64 + kt * 16) * 64 + j * 16], 64);
                    wmma::mma_sync(c[j], a, b, c[j]);
                }
            }
        }
        float* ob = out + ((size_t)b0 * NN + n) * DD;
#pragma unroll
        for (int j = 0; j < 4; ++j)
            wmma::store_matrix_sync(ob + j * 16, c[j], NN * DD, wmma::mem_row_major);
    }
}

// ---------------- launch ----------------
extern "C" void kernel_launch(void* const* d_in, const int* in_sizes, int n_in,
                              void* d_out, int out_size)
{
    const float* inputs  = (const float*)d_in[0];   // [B, N, D]
    const float* adj     = (const float*)d_in[1];   // [E]
    const int*   rows    = (const int*)d_in[2];     // [E]
    const int*   cols    = (const int*)d_in[3];     // [E]
    const float* weights = (const float*)d_in[4];   // [D*M, OUT]
    const float* biases  = (const float*)d_in[5];   // [1, OUT]
    float* out = (float*)d_out;                     // [B, N, OUT]
    (void)in_sizes; (void)n_in; (void)out_size;

    void *pP1, *pP2, *pS1, *pS2, *pV1, *pV2, *pX, *pT1, *pT2, *pT3, *pT4;
    cudaGetSymbolAddress(&pP1, g_ptr1);
    cudaGetSymbolAddress(&pP2, g_ptr2);
    cudaGetSymbolAddress(&pS1, g_src1);
    cudaGetSymbolAddress(&pS2, g_src2);
    cudaGetSymbolAddress(&pV1, g_val1);
    cudaGetSymbolAddress(&pV2, g_val2);
    cudaGetSymbolAddress(&pX,  g_Xh);
    cudaGetSymbolAddress(&pT1, g_T1);
    cudaGetSymbolAddress(&pT2, g_T2);
    cudaGetSymbolAddress(&pT3, g_T3);
    cudaGetSymbolAddress(&pT4, g_T4);

    k_zero<<<(NN + 255) / 256, 256>>>();
    // degree atomics + FULL X convert, fused
    k_pre<<<EDGE_BLOCKS + CVT_BLOCKS, 256>>>(rows, cols, adj, inputs);
    k_scan<<<dim3(16, 2), 1024>>>();
    k_fill<<<(EE + 255) / 256, 256>>>(rows, cols, adj);

    dim3 sg(NN / 8, 8);
    // pass1: T1 = S1 @ X0    (T1 gathered by later passes -> cached store)
    k_spmm<false, false><<<sg, 256>>>((const int*)pP1, (const int*)pS1, (const float*)pV1,
                                      (const __half*)pX, nullptr, (__half*)pT1);
    // pass2 ∥ pass3 fused: T2 = 2*S1@T1 - X0 ; T3 = S2@T1
    dim3 sg23(NN / 8, 8, 2);
    k_spmm23<<<sg23, 256>>>((const int*)pP1, (const int*)pS1, (const float*)pV1,
                            (const int*)pP2, (const int*)pS2, (const float*)pV2,
                            (const __half*)pT1, (const __half*)pX,
                            (__half*)pT2, (__half*)pT3);
    // pass4: T4 = 2*S2 @ T3 - T1   (T4 only read by GEMM -> streaming store)
    k_spmm<true, true><<<sg, 256>>>((const int*)pP2, (const int*)pS2, (const float*)pV2,
                                    (const __half*)pT3, (const __half*)pT1, (__half*)pT4);

    k_gemm_tc<<<(BB * NN) / (4 * 8 * 16), 256>>>((const __half*)pX, (const __half*)pT1,
                                                 (const __half*)pT2, (const __half*)pT3,
                                                 (const __half*)pT4, weights, biases, out);
}